// round 10
// baseline (speedup 1.0000x reference)
#include <cuda_runtime.h>
#include <math.h>

#define NN 2048          // nodes
#define MM 512           // groups
#define DD 32            // per-manifold dim
#define NSEG 32          // k-segments for CSC build
#define SEGLEN 64        // NN / NSEG
#define CAP 256          // member cache capacity in agg1
#define PT 257           // padded stride for agg1 transposed cache
#define CAP2 56          // member cache capacity per row in agg2
#define ST2 57           // padded stride for agg2 transposed cache
#define GRID 512
#define FULL 0xffffffffu

// role split within phase P (512 blocks)
#define CSR_BLOCKS 256   // 8 rows/block (warp per row)
#define CSC_BLOCKS 128   // 32 segs x 4 column-quarters
#define TRF_BLOCKS 128   // 16 rows/block (2 rows per warp)

// ---------------- device scratch (no allocs allowed) ----------------
__device__ float g_xs[NN*DD], g_xe[NN*DD];
__device__ float g_lamx[NN*DD];
__device__ float g_lamm1[NN];

__device__ int   g_csr[NN*MM];
__device__ int   g_csr_cnt[NN];
__device__ int   g_csc[MM*NN];
__device__ int   g_csc_cnt[MM*NSEG];

__device__ float g_es[MM*DD], g_ee[MM*DD];
__device__ float g_elamx[MM*DD];
__device__ float g_elamm1[MM];

__device__ unsigned g_bar;   // monotonic grid-barrier counter (never reset)

// ---------------- helpers ----------------
__device__ __forceinline__ float wsum(float v) {
    #pragma unroll
    for (int o = 16; o; o >>= 1) v += __shfl_xor_sync(FULL, v, o);
    return v;
}
__device__ __forceinline__ float clip1(float v) {
    return fminf(fmaxf(v, -1.0f + 1e-6f), 1.0f - 1e-6f);
}
// Device-wide barrier. All GRID blocks are resident (launch_bounds guarantees
// >= 4 blocks/SM * 148 SMs = 592 >= 512), so spinning is safe.
__device__ __forceinline__ void grid_bar() {
    __syncthreads();
    __threadfence();
    if (threadIdx.x == 0) {
        unsigned old = atomicAdd(&g_bar, 1u);
        unsigned target = (old & ~511u) + 512u;
        while (*(volatile unsigned*)&g_bar < target) {}
    }
    __syncthreads();
}

// ---------------- shared-memory overlays (union via raw buffer) ----------------
struct SmemP {
    float sW[3 * DD * DD];
    float sB[3 * DD];
};
struct SmemA1 {
    float pT[DD * PT];
    float a[CAP], ad[CAP], ar[CAP];
    float mu[DD];
    float vec[8][3][DD];
    float sc[8], tw[8][DD], bw[8], brw[8];
    int   cnt[NSEG], off[NSEG], list[CAP], tot;
};
struct SmemA2 {
    float pT[4][DD * ST2];
    float a[4][CAP2];
    float mu[4][DD];
};

// ---------------- fused persistent kernel ----------------
__global__ __launch_bounds__(256, 4) void k_fused(
        const float* __restrict__ x,
        const float* __restrict__ H,
        const float* __restrict__ Wh, const float* __restrict__ bh,
        const float* __restrict__ Ws, const float* __restrict__ bs,
        const float* __restrict__ We, const float* __restrict__ be,
        const float* __restrict__ cph,
        float* __restrict__ out) {
    __shared__ __align__(16) unsigned char s_raw[42496];

    int b    = blockIdx.x;
    int tid  = threadIdx.x;
    int w    = tid >> 5;
    int lane = tid & 31;

    float c  = fabsf(*cph) + 1e-6f;
    float sc = sqrtf(c);
    float maxn = (1.0f - 1e-5f) / sc;

    // ================= phase P: csr | csc | transform =================
    if (b < CSR_BLOCKS) {
        // ---- CSR: warp per row; parallel extraction via ballot-word scan ----
        int row = b * 8 + w;
        const float* rp = H + (size_t)row * MM;
        float h[16];
        #pragma unroll
        for (int j = 0; j < 16; j++) h[j] = rp[j * 32 + lane];   // MLP 16
        unsigned myword = 0;
        #pragma unroll
        for (int j = 0; j < 16; j++) {
            unsigned m = __ballot_sync(FULL, h[j] > 0.5f);
            if (lane == j) myword = m;
        }
        int pc = (lane < 16) ? __popc(myword) : 0;
        int incl = pc;
        #pragma unroll
        for (int o = 1; o < 32; o <<= 1) {
            int vv = __shfl_up_sync(FULL, incl, o);
            if (lane >= o) incl += vv;
        }
        int excl = incl - pc;
        int cnt  = __shfl_sync(FULL, incl, 15);
        if (lane < 16) {
            unsigned word = myword;
            int off  = excl;
            int base = lane * 32;
            while (word) {
                g_csr[row * MM + off++] = base + __ffs(word) - 1;
                word &= word - 1;
            }
        }
        if (lane == 0) g_csr_cnt[row] = cnt;
    } else if (b < CSR_BLOCKS + CSC_BLOCKS) {
        // ---- CSC: 32 segs x 4 column-quarters; 128 active threads ----
        int rel = b - CSR_BLOCKS;
        int seg = rel >> 2;
        int q   = rel & 3;
        if (tid < 128) {
            int g    = q * 128 + tid;
            int cnt  = 0;
            int base = g * NN + seg * SEGLEN;
            int k0   = seg * SEGLEN;
            for (int j0 = 0; j0 < SEGLEN; j0 += 8) {
                float h[8];
                #pragma unroll
                for (int u = 0; u < 8; u++)
                    h[u] = H[(size_t)(k0 + j0 + u) * MM + g];
                #pragma unroll
                for (int u = 0; u < 8; u++)
                    if (h[u] > 0.5f) g_csc[base + cnt++] = k0 + j0 + u;
            }
            g_csc_cnt[g * NSEG + seg] = cnt;
        }
    } else {
        // ---- transform: 16 rows/block, 2 rows per warp ----
        SmemP* S = (SmemP*)s_raw;
        for (int i = tid; i < DD * DD; i += blockDim.x) {
            S->sW[i]             = Wh[i];
            S->sW[DD*DD + i]     = Ws[i];
            S->sW[2*DD*DD + i]   = We[i];
        }
        if (tid < DD) {
            S->sB[tid]        = bh[tid];
            S->sB[DD + tid]   = bs[tid];
            S->sB[2*DD + tid] = be[tid];
        }
        __syncthreads();

        int r0 = (b - CSR_BLOCKS - CSC_BLOCKS) * 16;
        #pragma unroll
        for (int rr = 0; rr < 2; rr++) {
            int r = r0 + w + rr * 8;

            float xh = x[r * 96 + lane];
            float xs = x[r * 96 + 32 + lane];
            float xe = x[r * 96 + 64 + lane];

            // hyp_project(x_h)
            float n  = sqrtf(wsum(xh * xh));
            float nm = fmaxf(n, 1e-6f);
            if (nm > maxn) xh *= maxn / nm;

            // logmap0
            n = fmaxf(sqrtf(wsum(xh * xh)), 1e-6f);
            float arg = clip1(sc * n);
            float lg  = atanhf(arg) * xh / (sc * n);

            // v = lg @ Wh^T + bh
            float v = S->sB[lane];
            #pragma unroll
            for (int i = 0; i < DD; i++)
                v = fmaf(__shfl_sync(FULL, lg, i), S->sW[lane * DD + i], v);

            // expmap0
            n = fmaxf(sqrtf(wsum(v * v)), 1e-6f);
            float xh2 = tanhf(sc * n) * v / (sc * n);
            // hyp_project
            n  = sqrtf(wsum(xh2 * xh2));
            nm = fmaxf(n, 1e-6f);
            if (nm > maxn) xh2 *= maxn / nm;

            float sq  = wsum(xh2 * xh2);
            float lam = 2.0f / fmaxf(1.0f - c * sq, 1e-6f);
            g_lamx[r * DD + lane] = lam * xh2;
            if (lane == 0) g_lamm1[r] = lam - 1.0f;

            // sphere branch
            n = fmaxf(sqrtf(wsum(xs * xs)), 1e-6f);
            xs /= n;
            float s2 = S->sB[DD + lane];
            #pragma unroll
            for (int i = 0; i < DD; i++)
                s2 = fmaf(__shfl_sync(FULL, xs, i), S->sW[DD*DD + lane * DD + i], s2);
            n = fmaxf(sqrtf(wsum(s2 * s2)), 1e-6f);
            s2 /= n;
            g_xs[r * DD + lane] = s2;   // unit norm: pp treated as 1 downstream

            // euclidean branch
            float e2 = S->sB[2*DD + lane];
            #pragma unroll
            for (int i = 0; i < DD; i++)
                e2 = fmaf(__shfl_sync(FULL, xe, i), S->sW[2*DD*DD + lane * DD + i], e2);
            g_xe[r * DD + lane] = e2;
        }
    }

    grid_bar();

    // ================= phase A1: block = group =================
    {
        SmemA1* S = (SmemA1*)s_raw;
        int g = b;

        // segment offsets via warp-0 prefix scan
        if (w == 0) {
            int s = g_csc_cnt[g * NSEG + lane];
            S->cnt[lane] = s;
            int incl = s;
            #pragma unroll
            for (int o = 1; o < 32; o <<= 1) {
                int vv = __shfl_up_sync(FULL, incl, o);
                if (lane >= o) incl += vv;
            }
            S->off[lane] = incl - s;
            if (lane == 31) S->tot = incl;
        }
        __syncthreads();
        int tot = S->tot;
        bool cache = (tot <= CAP);
        float cntf = (float)tot;

        // flatten member list (32 threads, one segment each)
        if (cache && tid < NSEG) {
            int cnt = S->cnt[tid], off = S->off[tid];
            const int* lst = g_csc + g * NN + tid * SEGLEN;
            for (int j = 0; j < cnt; j++) S->list[off + j] = lst[j];
        }
        __syncthreads();

        // phase A: linear sums + transposed SMEM member cache (2-way ILP)
        float sp = 0.f, sl = 0.f, se = 0.f, sm = 0.f;
        if (cache) {
            int m = w;
            for (; m + 8 < tot; m += 16) {
                int k0 = S->list[m], k1 = S->list[m + 8];
                float p0 = g_xs[k0 * DD + lane];
                float p1 = g_xs[k1 * DD + lane];
                float l0 = g_lamx[k0 * DD + lane];
                float l1 = g_lamx[k1 * DD + lane];
                float e0 = g_xe[k0 * DD + lane];
                float e1 = g_xe[k1 * DD + lane];
                sp += p0 + p1;
                sl += l0 + l1;
                se += e0 + e1;
                sm += g_lamm1[k0] + g_lamm1[k1];
                S->pT[lane * PT + m]     = p0;
                S->pT[lane * PT + m + 8] = p1;
            }
            if (m < tot) {
                int k = S->list[m];
                float p = g_xs[k * DD + lane];
                sp += p;
                sl += g_lamx[k * DD + lane];
                se += g_xe[k * DD + lane];
                sm += g_lamm1[k];
                S->pT[lane * PT + m] = p;
            }
        } else {
            for (int seg = w; seg < NSEG; seg += 8) {
                int cnt = S->cnt[seg];
                const int* lst = g_csc + g * NN + seg * SEGLEN;
                for (int j = 0; j < cnt; j++) {
                    int k = lst[j];
                    sp += g_xs[k * DD + lane];
                    sl += g_lamx[k * DD + lane];
                    se += g_xe[k * DD + lane];
                    sm += g_lamm1[k];
                }
            }
        }
        S->vec[w][0][lane] = sp;
        S->vec[w][1][lane] = sl;
        S->vec[w][2][lane] = se;
        if (lane == 0) S->sc[w] = sm;
        __syncthreads();

        if (w == 0) {
            float tp = 0.f, tl = 0.f, te = 0.f, tm = 0.f;
            #pragma unroll
            for (int u = 0; u < 8; u++) {
                tp += S->vec[u][0][lane];
                tl += S->vec[u][1][lane];
                te += S->vec[u][2][lane];
                tm += S->sc[u];
            }
            g_ee[g * DD + lane] = te / fmaxf(cntf, 1e-6f);

            // gyromidpoint
            float den = fmaxf(tm, 1e-6f);
            float y   = tl / den;
            float yn  = fmaxf(sqrtf(wsum(y * y)), 1e-6f);
            float arg = clip1(sc * yn);
            float eh  = tanhf(0.5f * atanhf(arg)) * y / (sc * yn);
            float sq  = wsum(eh * eh);
            float lam = 2.0f / fmaxf(1.0f - c * sq, 1e-6f);
            g_elamx[g * DD + lane] = lam * eh;
            if (lane == 0) g_elamm1[g] = lam - 1.0f;

            // sphere mu0 (unit norm => mm == 1 henceforth)
            float mu = tp / cntf;
            mu /= fmaxf(sqrtf(wsum(mu * mu)), 1e-6f);
            S->mu[lane] = mu;
        }
        __syncthreads();

        // phase B: 5 Frechet iterations (w0-only epilogue)
        for (int it = 0; it < 5; it++) {
            if (cache) {
                for (int m = tid; m < tot; m += 256) {
                    float d0 = 0.f, d1 = 0.f;
                    #pragma unroll
                    for (int d = 0; d < DD; d += 2) {
                        d0 = fmaf(S->mu[d],     S->pT[d * PT + m],       d0);
                        d1 = fmaf(S->mu[d + 1], S->pT[(d + 1) * PT + m], d1);
                    }
                    float draw = d0 + d1;
                    float dotc = clip1(draw);
                    float theta = acosf(dotc);
                    float dn2 = 1.0f - dotc * (2.0f * draw - dotc);
                    float dn  = fmaxf(sqrtf(fmaxf(dn2, 0.f)), 1e-6f);
                    float a   = theta / dn;
                    S->a[m]  = a;
                    S->ad[m] = a * dotc;
                    S->ar[m] = a * draw;
                }
                __syncthreads();
                float tpart = 0.f, bpart = 0.f, brpart = 0.f;
                for (int m = w; m < tot; m += 8) {
                    tpart  = fmaf(S->a[m], S->pT[lane * PT + m], tpart);
                    bpart  += S->ad[m];
                    brpart += S->ar[m];
                }
                S->tw[w][lane] = tpart;
                if (lane == 0) { S->bw[w] = bpart; S->brw[w] = brpart; }
            } else {
                float mu = S->mu[lane];
                float t = 0.f, bsum = 0.f, brsum = 0.f;
                for (int seg = w; seg < NSEG; seg += 8) {
                    int cnt = S->cnt[seg];
                    const int* lst = g_csc + g * NN + seg * SEGLEN;
                    for (int j = 0; j < cnt; j++) {
                        int k = lst[j];
                        float p    = g_xs[k * DD + lane];
                        float draw = wsum(mu * p);
                        float dotc = clip1(draw);
                        float theta = acosf(dotc);
                        float dn2 = 1.0f - dotc * (2.0f * draw - dotc);
                        float dn  = fmaxf(sqrtf(fmaxf(dn2, 0.f)), 1e-6f);
                        float a   = theta / dn;
                        t     = fmaf(a, p, t);
                        bsum  += a * dotc;
                        brsum += a * draw;
                    }
                }
                S->tw[w][lane] = t;
                if (lane == 0) { S->bw[w] = bsum; S->brw[w] = brsum; }
            }
            __syncthreads();
            if (w == 0) {
                float mu = S->mu[lane];
                float tsum = 0.f, bt = 0.f, br = 0.f;
                #pragma unroll
                for (int u = 0; u < 8; u++) { tsum += S->tw[u][lane]; bt += S->bw[u]; br += S->brw[u]; }
                float t = fmaf(-bt, mu, tsum);
                float avg = t / cntf;
                float vn2 = wsum(avg * avg);
                float vn  = sqrtf(vn2);
                float vns = fmaxf(vn, 1e-6f);
                float cv = cosf(vn), sv = sinf(vn);
                float mudotavg = (br - bt) / cntf;
                float r   = cv * mu + sv * avg / vns;
                float svv = sv / vns;
                float rn2 = fmaf(cv * cv, 1.0f, fmaf(2.0f * cv * svv, mudotavg, svv * svv * vn2));
                float rn  = fmaxf(sqrtf(rn2), 1e-6f);
                S->mu[lane] = r / rn;
            }
            __syncthreads();
        }
        if (w == 0) g_es[g * DD + lane] = S->mu[lane];
    }

    grid_bar();

    // ================= phase A2: 4 rows/block, warps 0-3 =================
    if (w < 4) {
        SmemA2* S = (SmemA2*)s_raw;
        int i = b * 4 + w;

        int cnt = g_csr_cnt[i];
        const int* lst = g_csr + i * MM;
        bool cache = (cnt <= CAP2);
        float cntf = (float)cnt;

        float sp = 0.f, sl = 0.f, se = 0.f, sm = 0.f;
        if (cache) {
            int j = 0;
            for (; j + 1 < cnt; j += 2) {
                int g0 = lst[j], g1 = lst[j + 1];
                float p0 = g_es[g0 * DD + lane];
                float p1 = g_es[g1 * DD + lane];
                float l0 = g_elamx[g0 * DD + lane];
                float l1 = g_elamx[g1 * DD + lane];
                float e0 = g_ee[g0 * DD + lane];
                float e1 = g_ee[g1 * DD + lane];
                sp += p0 + p1;
                sl += l0 + l1;
                se += e0 + e1;
                sm += g_elamm1[g0] + g_elamm1[g1];
                S->pT[w][lane * ST2 + j]     = p0;
                S->pT[w][lane * ST2 + j + 1] = p1;
            }
            if (j < cnt) {
                int g0 = lst[j];
                float p = g_es[g0 * DD + lane];
                sp += p;
                sl += g_elamx[g0 * DD + lane];
                se += g_ee[g0 * DD + lane];
                sm += g_elamm1[g0];
                S->pT[w][lane * ST2 + j] = p;
            }
        } else {
            for (int j = 0; j < cnt; j++) {
                int g0 = lst[j];
                sp += g_es[g0 * DD + lane];
                sl += g_elamx[g0 * DD + lane];
                se += g_ee[g0 * DD + lane];
                sm += g_elamm1[g0];
            }
        }

        float oe = se / fmaxf(cntf, 1e-6f);

        // gyromidpoint + final hyp_project
        float den = fmaxf(sm, 1e-6f);
        float y   = sl / den;
        float yn  = fmaxf(sqrtf(wsum(y * y)), 1e-6f);
        float arg = clip1(sc * yn);
        float oh  = tanhf(0.5f * atanhf(arg)) * y / (sc * yn);
        float n   = sqrtf(wsum(oh * oh));
        float nm  = fmaxf(n, 1e-6f);
        if (nm > maxn) oh *= maxn / nm;

        // sphere midpoint
        float mu = sp / cntf;
        mu /= fmaxf(sqrtf(wsum(mu * mu)), 1e-6f);

        if (cache) {
            S->mu[w][lane] = mu;
            __syncwarp();
            for (int it = 0; it < 5; it++) {
                float asum_d = 0.f, asum_r = 0.f;
                for (int m = lane; m < cnt; m += 32) {
                    float d0 = 0.f, d1 = 0.f;
                    #pragma unroll
                    for (int d = 0; d < DD; d += 2) {
                        d0 = fmaf(S->mu[w][d],     S->pT[w][d * ST2 + m],       d0);
                        d1 = fmaf(S->mu[w][d + 1], S->pT[w][(d + 1) * ST2 + m], d1);
                    }
                    float draw = d0 + d1;
                    float dotc = clip1(draw);
                    float theta = acosf(dotc);
                    float dn2 = 1.0f - dotc * (2.0f * draw - dotc);
                    float dn  = fmaxf(sqrtf(fmaxf(dn2, 0.f)), 1e-6f);
                    float a   = theta / dn;
                    S->a[w][m] = a;
                    asum_d = fmaf(a, dotc, asum_d);
                    asum_r = fmaf(a, draw, asum_r);
                }
                __syncwarp();
                float bt = wsum(asum_d);
                float br = wsum(asum_r);
                float t0 = 0.f, t1 = 0.f;
                int m = 0;
                for (; m + 1 < cnt; m += 2) {
                    t0 = fmaf(S->a[w][m],     S->pT[w][lane * ST2 + m],     t0);
                    t1 = fmaf(S->a[w][m + 1], S->pT[w][lane * ST2 + m + 1], t1);
                }
                if (m < cnt) t0 = fmaf(S->a[w][m], S->pT[w][lane * ST2 + m], t0);
                float mul = S->mu[w][lane];
                float t = fmaf(-bt, mul, t0 + t1);
                float avg = t / cntf;
                float vn2 = wsum(avg * avg);
                float vn  = sqrtf(vn2);
                float vns = fmaxf(vn, 1e-6f);
                float cv = cosf(vn), sv = sinf(vn);
                float mudotavg = (br - bt) / cntf;
                float r   = cv * mul + sv * avg / vns;
                float svv = sv / vns;
                float rn2 = fmaf(cv * cv, 1.0f, fmaf(2.0f * cv * svv, mudotavg, svv * svv * vn2));
                float rn  = fmaxf(sqrtf(rn2), 1e-6f);
                mul = r / rn;
                S->mu[w][lane] = mul;
                __syncwarp();
            }
            mu = S->mu[w][lane];
        } else {
            for (int it = 0; it < 5; it++) {
                float mm = wsum(mu * mu);
                float t = 0.f, bsum = 0.f;
                for (int j = 0; j < cnt; j++) {
                    int g0 = lst[j];
                    float p0 = g_es[g0 * DD + lane];
                    float w0 = wsum(mu * p0);
                    float dc0 = clip1(w0);
                    float th0 = acosf(dc0);
                    float q0 = 1.0f - dc0 * (2.0f * w0 - dc0 * mm);
                    float a0 = th0 / fmaxf(sqrtf(fmaxf(q0, 0.f)), 1e-6f);
                    t    = fmaf(a0, p0, t);
                    bsum = fmaf(-a0, dc0, bsum);
                }
                t = fmaf(bsum, mu, t);
                t /= cntf;
                float vn  = sqrtf(wsum(t * t));
                float vns = fmaxf(vn, 1e-6f);
                mu = cosf(vn) * mu + sinf(vn) * t / vns;
                mu /= fmaxf(sqrtf(wsum(mu * mu)), 1e-6f);
            }
        }
        float os = mu / fmaxf(sqrtf(wsum(mu * mu)), 1e-6f);

        out[i * 96 + lane]      = oh;
        out[i * 96 + 32 + lane] = os;
        out[i * 96 + 64 + lane] = oe;
    }
}

// ---------------- launch ----------------
extern "C" void kernel_launch(void* const* d_in, const int* in_sizes, int n_in,
                              void* d_out, int out_size) {
    const float* x   = (const float*)d_in[0];
    const float* H   = (const float*)d_in[1];
    const float* Wh  = (const float*)d_in[2];
    const float* bh  = (const float*)d_in[3];
    const float* Ws  = (const float*)d_in[4];
    const float* bs  = (const float*)d_in[5];
    const float* We  = (const float*)d_in[6];
    const float* be  = (const float*)d_in[7];
    const float* c_h = (const float*)d_in[8];
    float* out = (float*)d_out;

    k_fused<<<GRID, 256>>>(x, H, Wh, bh, Ws, bs, We, be, c_h, out);
}

// round 11
// speedup vs baseline: 1.0858x; 1.0858x over previous
#include <cuda_runtime.h>
#include <math.h>

#define NN 2048          // nodes
#define MM 512           // groups
#define DD 32            // per-manifold dim
#define NSEG 32          // k-segments for CSC build
#define SEGLEN 64        // NN / NSEG
#define CAP 256          // member cache capacity in agg1
#define PT 257           // padded stride for agg1 transposed cache
#define CAP2 56          // member cache capacity per row in agg2
#define ST2 57           // padded stride for agg2 transposed cache
#define AGRID 512
#define FULL 0xffffffffu

// grid-role split for fused pre kernel
#define CSR_BLOCKS 256   // 8 rows/block (warp per row)
#define CSC_BLOCKS 64    // 32 segs x 2 column-halves
#define TRF_BLOCKS 256   // 8 rows/block
#define PRE_BLOCKS (CSR_BLOCKS + CSC_BLOCKS + TRF_BLOCKS)

// ---------------- device scratch (no allocs allowed) ----------------
__device__ float g_xs[NN*DD], g_xe[NN*DD];
__device__ float g_lamx[NN*DD];
__device__ float g_lamm1[NN];

__device__ int   g_csr[NN*MM];
__device__ int   g_csr_cnt[NN];
__device__ int   g_csc[MM*NN];
__device__ int   g_csc_cnt[MM*NSEG];

__device__ float g_es[MM*DD], g_ee[MM*DD];
__device__ float g_elamx[MM*DD];
__device__ float g_elamm1[MM];

__device__ unsigned g_bar;   // monotonic grid-barrier counter (never reset)

// ---------------- helpers ----------------
__device__ __forceinline__ float wsum(float v) {
    #pragma unroll
    for (int o = 16; o; o >>= 1) v += __shfl_xor_sync(FULL, v, o);
    return v;
}
__device__ __forceinline__ float clip1(float v) {
    return fminf(fmaxf(v, -1.0f + 1e-6f), 1.0f - 1e-6f);
}

// ---------------- fused pre kernel: csr | csc | transform (R9 verbatim) ----
__global__ __launch_bounds__(256) void k_pre(const float* __restrict__ x,
                          const float* __restrict__ H,
                          const float* __restrict__ Wh, const float* __restrict__ bh,
                          const float* __restrict__ Ws, const float* __restrict__ bs,
                          const float* __restrict__ We, const float* __restrict__ be,
                          const float* __restrict__ cph) {
    int b = blockIdx.x;
    int lane = threadIdx.x & 31;
    if (b < CSR_BLOCKS) {
        int row = b * 8 + (threadIdx.x >> 5);
        const float* rp = H + (size_t)row * MM;
        float h[16];
        #pragma unroll
        for (int j = 0; j < 16; j++) h[j] = rp[j * 32 + lane];   // MLP 16
        unsigned myword = 0;
        #pragma unroll
        for (int j = 0; j < 16; j++) {
            unsigned m = __ballot_sync(FULL, h[j] > 0.5f);
            if (lane == j) myword = m;
        }
        int pc = (lane < 16) ? __popc(myword) : 0;
        int incl = pc;
        #pragma unroll
        for (int o = 1; o < 32; o <<= 1) {
            int vv = __shfl_up_sync(FULL, incl, o);
            if (lane >= o) incl += vv;
        }
        int excl = incl - pc;
        int cnt  = __shfl_sync(FULL, incl, 15);
        if (lane < 16) {
            unsigned word = myword;
            int off  = excl;
            int base = lane * 32;
            while (word) {
                g_csr[row * MM + off++] = base + __ffs(word) - 1;
                word &= word - 1;
            }
        }
        if (lane == 0) g_csr_cnt[row] = cnt;
        return;
    }
    if (b < CSR_BLOCKS + CSC_BLOCKS) {
        int rel  = b - CSR_BLOCKS;
        int seg  = rel >> 1;
        int g    = ((rel & 1) << 8) + threadIdx.x;      // 0..511
        int cnt  = 0;
        int base = g * NN + seg * SEGLEN;
        int k0   = seg * SEGLEN;
        for (int j0 = 0; j0 < SEGLEN; j0 += 8) {
            float h[8];
            #pragma unroll
            for (int u = 0; u < 8; u++)
                h[u] = H[(size_t)(k0 + j0 + u) * MM + g];
            #pragma unroll
            for (int u = 0; u < 8; u++)
                if (h[u] > 0.5f) g_csc[base + cnt++] = k0 + j0 + u;
        }
        g_csc_cnt[g * NSEG + seg] = cnt;
        return;
    }
    // ---- transform: warp per row, 8 rows/block ----
    __shared__ float sW[3 * DD * DD];
    __shared__ float sB[3 * DD];
    for (int i = threadIdx.x; i < DD * DD; i += blockDim.x) {
        sW[i]             = Wh[i];
        sW[DD*DD + i]     = Ws[i];
        sW[2*DD*DD + i]   = We[i];
    }
    if (threadIdx.x < DD) {
        sB[threadIdx.x]        = bh[threadIdx.x];
        sB[DD + threadIdx.x]   = bs[threadIdx.x];
        sB[2*DD + threadIdx.x] = be[threadIdx.x];
    }
    __syncthreads();

    int r = (b - CSR_BLOCKS - CSC_BLOCKS) * 8 + (threadIdx.x >> 5);

    float c  = fabsf(*cph) + 1e-6f;
    float sc = sqrtf(c);
    float maxn = (1.0f - 1e-5f) / sc;

    float xh = x[r * 96 + lane];
    float xs = x[r * 96 + 32 + lane];
    float xe = x[r * 96 + 64 + lane];

    float n  = sqrtf(wsum(xh * xh));
    float nm = fmaxf(n, 1e-6f);
    if (nm > maxn) xh *= maxn / nm;

    n = fmaxf(sqrtf(wsum(xh * xh)), 1e-6f);
    float arg = clip1(sc * n);
    float lg  = atanhf(arg) * xh / (sc * n);

    float v = sB[lane];
    #pragma unroll
    for (int i = 0; i < DD; i++)
        v = fmaf(__shfl_sync(FULL, lg, i), sW[lane * DD + i], v);

    n = fmaxf(sqrtf(wsum(v * v)), 1e-6f);
    float xh2 = tanhf(sc * n) * v / (sc * n);
    n  = sqrtf(wsum(xh2 * xh2));
    nm = fmaxf(n, 1e-6f);
    if (nm > maxn) xh2 *= maxn / nm;

    float sq  = wsum(xh2 * xh2);
    float lam = 2.0f / fmaxf(1.0f - c * sq, 1e-6f);
    g_lamx[r * DD + lane] = lam * xh2;
    if (lane == 0) g_lamm1[r] = lam - 1.0f;

    n = fmaxf(sqrtf(wsum(xs * xs)), 1e-6f);
    xs /= n;
    float s2 = sB[DD + lane];
    #pragma unroll
    for (int i = 0; i < DD; i++)
        s2 = fmaf(__shfl_sync(FULL, xs, i), sW[DD*DD + lane * DD + i], s2);
    n = fmaxf(sqrtf(wsum(s2 * s2)), 1e-6f);
    s2 /= n;
    g_xs[r * DD + lane] = s2;      // unit norm: pp treated as 1 downstream

    float e2 = sB[2*DD + lane];
    #pragma unroll
    for (int i = 0; i < DD; i++)
        e2 = fmaf(__shfl_sync(FULL, xe, i), sW[2*DD*DD + lane * DD + i], e2);
    g_xe[r * DD + lane] = e2;
}

// ---------------- shared-memory overlays for fused agg ----------------
struct SmemA1 {
    float pT[DD * PT];
    float a[CAP], ad[CAP], ar[CAP];
    float mu[DD];
    float vec[8][3][DD];
    float sc[8], tw[8][DD], bw[8], brw[8];
    int   cnt[NSEG], off[NSEG], list[CAP], tot;
};
struct SmemA2 {
    float pT[4][DD * ST2];
    float a[4][CAP2];
    float mu[4][DD];
};

// ---------------- fused aggregation: A1 (block=group) | bar | A2 (4 rows) ----
__global__ __launch_bounds__(256, 4) void k_agg(const float* __restrict__ cph,
                                                float* __restrict__ out) {
    __shared__ __align__(16) unsigned char s_raw[42496];

    int b    = blockIdx.x;
    int tid  = threadIdx.x;
    int w    = tid >> 5;
    int lane = tid & 31;

    float c  = fabsf(*cph) + 1e-6f;
    float sc = sqrtf(c);
    float maxn = (1.0f - 1e-5f) / sc;

    // ================= phase A1: block = group =================
    {
        SmemA1* S = (SmemA1*)s_raw;
        int g = b;

        if (w == 0) {
            int s = g_csc_cnt[g * NSEG + lane];
            S->cnt[lane] = s;
            int incl = s;
            #pragma unroll
            for (int o = 1; o < 32; o <<= 1) {
                int vv = __shfl_up_sync(FULL, incl, o);
                if (lane >= o) incl += vv;
            }
            S->off[lane] = incl - s;
            if (lane == 31) S->tot = incl;
        }
        __syncthreads();
        int tot = S->tot;
        bool cache = (tot <= CAP);
        float cntf = (float)tot;

        if (cache && tid < NSEG) {
            int cnt = S->cnt[tid], off = S->off[tid];
            const int* lst = g_csc + g * NN + tid * SEGLEN;
            for (int j = 0; j < cnt; j++) S->list[off + j] = lst[j];
        }
        __syncthreads();

        float sp = 0.f, sl = 0.f, se = 0.f, sm = 0.f;
        if (cache) {
            int m = w;
            for (; m + 8 < tot; m += 16) {
                int k0 = S->list[m], k1 = S->list[m + 8];
                float p0 = g_xs[k0 * DD + lane];
                float p1 = g_xs[k1 * DD + lane];
                float l0 = g_lamx[k0 * DD + lane];
                float l1 = g_lamx[k1 * DD + lane];
                float e0 = g_xe[k0 * DD + lane];
                float e1 = g_xe[k1 * DD + lane];
                sp += p0 + p1;
                sl += l0 + l1;
                se += e0 + e1;
                sm += g_lamm1[k0] + g_lamm1[k1];
                S->pT[lane * PT + m]     = p0;
                S->pT[lane * PT + m + 8] = p1;
            }
            if (m < tot) {
                int k = S->list[m];
                float p = g_xs[k * DD + lane];
                sp += p;
                sl += g_lamx[k * DD + lane];
                se += g_xe[k * DD + lane];
                sm += g_lamm1[k];
                S->pT[lane * PT + m] = p;
            }
        } else {
            for (int seg = w; seg < NSEG; seg += 8) {
                int cnt = S->cnt[seg];
                const int* lst = g_csc + g * NN + seg * SEGLEN;
                for (int j = 0; j < cnt; j++) {
                    int k = lst[j];
                    sp += g_xs[k * DD + lane];
                    sl += g_lamx[k * DD + lane];
                    se += g_xe[k * DD + lane];
                    sm += g_lamm1[k];
                }
            }
        }
        S->vec[w][0][lane] = sp;
        S->vec[w][1][lane] = sl;
        S->vec[w][2][lane] = se;
        if (lane == 0) S->sc[w] = sm;
        __syncthreads();

        if (w == 0) {
            float tp = 0.f, tl = 0.f, te = 0.f, tm = 0.f;
            #pragma unroll
            for (int u = 0; u < 8; u++) {
                tp += S->vec[u][0][lane];
                tl += S->vec[u][1][lane];
                te += S->vec[u][2][lane];
                tm += S->sc[u];
            }
            g_ee[g * DD + lane] = te / fmaxf(cntf, 1e-6f);

            float den = fmaxf(tm, 1e-6f);
            float y   = tl / den;
            float yn  = fmaxf(sqrtf(wsum(y * y)), 1e-6f);
            float arg = clip1(sc * yn);
            float eh  = tanhf(0.5f * atanhf(arg)) * y / (sc * yn);
            float sq  = wsum(eh * eh);
            float lam = 2.0f / fmaxf(1.0f - c * sq, 1e-6f);
            g_elamx[g * DD + lane] = lam * eh;
            if (lane == 0) g_elamm1[g] = lam - 1.0f;

            float mu = tp / cntf;
            mu /= fmaxf(sqrtf(wsum(mu * mu)), 1e-6f);
            S->mu[lane] = mu;
        }
        __syncthreads();

        for (int it = 0; it < 5; it++) {
            if (cache) {
                for (int m = tid; m < tot; m += 256) {
                    float d0 = 0.f, d1 = 0.f;
                    #pragma unroll
                    for (int d = 0; d < DD; d += 2) {
                        d0 = fmaf(S->mu[d],     S->pT[d * PT + m],       d0);
                        d1 = fmaf(S->mu[d + 1], S->pT[(d + 1) * PT + m], d1);
                    }
                    float draw = d0 + d1;
                    float dotc = clip1(draw);
                    float theta = acosf(dotc);
                    float dn2 = 1.0f - dotc * (2.0f * draw - dotc);
                    float dn  = fmaxf(sqrtf(fmaxf(dn2, 0.f)), 1e-6f);
                    float a   = theta / dn;
                    S->a[m]  = a;
                    S->ad[m] = a * dotc;
                    S->ar[m] = a * draw;
                }
                __syncthreads();
                float tpart = 0.f, bpart = 0.f, brpart = 0.f;
                for (int m = w; m < tot; m += 8) {
                    tpart  = fmaf(S->a[m], S->pT[lane * PT + m], tpart);
                    bpart  += S->ad[m];
                    brpart += S->ar[m];
                }
                S->tw[w][lane] = tpart;
                if (lane == 0) { S->bw[w] = bpart; S->brw[w] = brpart; }
            } else {
                float mu = S->mu[lane];
                float t = 0.f, bsum = 0.f, brsum = 0.f;
                for (int seg = w; seg < NSEG; seg += 8) {
                    int cnt = S->cnt[seg];
                    const int* lst = g_csc + g * NN + seg * SEGLEN;
                    for (int j = 0; j < cnt; j++) {
                        int k = lst[j];
                        float p    = g_xs[k * DD + lane];
                        float draw = wsum(mu * p);
                        float dotc = clip1(draw);
                        float theta = acosf(dotc);
                        float dn2 = 1.0f - dotc * (2.0f * draw - dotc);
                        float dn  = fmaxf(sqrtf(fmaxf(dn2, 0.f)), 1e-6f);
                        float a   = theta / dn;
                        t     = fmaf(a, p, t);
                        bsum  += a * dotc;
                        brsum += a * draw;
                    }
                }
                S->tw[w][lane] = t;
                if (lane == 0) { S->bw[w] = bsum; S->brw[w] = brsum; }
            }
            __syncthreads();
            if (w == 0) {
                float mu = S->mu[lane];
                float tsum = 0.f, bt = 0.f, br = 0.f;
                #pragma unroll
                for (int u = 0; u < 8; u++) { tsum += S->tw[u][lane]; bt += S->bw[u]; br += S->brw[u]; }
                float t = fmaf(-bt, mu, tsum);
                float avg = t / cntf;
                float vn2 = wsum(avg * avg);
                float vn  = sqrtf(vn2);
                float vns = fmaxf(vn, 1e-6f);
                float cv = cosf(vn), sv = sinf(vn);
                float mudotavg = (br - bt) / cntf;
                float r   = cv * mu + sv * avg / vns;
                float svv = sv / vns;
                float rn2 = fmaf(cv * cv, 1.0f, fmaf(2.0f * cv * svv, mudotavg, svv * svv * vn2));
                float rn  = fmaxf(sqrtf(rn2), 1e-6f);
                S->mu[lane] = r / rn;
            }
            __syncthreads();
        }
        if (w == 0) g_es[g * DD + lane] = S->mu[lane];
    }

    // ---- grid barrier: all AGRID blocks resident (4 blocks/SM x 148 >= 512) ----
    __syncthreads();
    __threadfence();
    if (tid == 0) {
        unsigned old = atomicAdd(&g_bar, 1u);
        unsigned target = (old & ~(unsigned)(AGRID - 1)) + (unsigned)AGRID;
        while (*(volatile unsigned*)&g_bar < target) {}
    }
    __syncthreads();

    // ================= phase A2: 4 rows/block, warps 0-3 =================
    if (w < 4) {
        SmemA2* S = (SmemA2*)s_raw;
        int i = b * 4 + w;

        int cnt = g_csr_cnt[i];
        const int* lst = g_csr + i * MM;
        bool cache = (cnt <= CAP2);
        float cntf = (float)cnt;

        float sp = 0.f, sl = 0.f, se = 0.f, sm = 0.f;
        if (cache) {
            int j = 0;
            for (; j + 1 < cnt; j += 2) {
                int g0 = lst[j], g1 = lst[j + 1];
                float p0 = g_es[g0 * DD + lane];
                float p1 = g_es[g1 * DD + lane];
                float l0 = g_elamx[g0 * DD + lane];
                float l1 = g_elamx[g1 * DD + lane];
                float e0 = g_ee[g0 * DD + lane];
                float e1 = g_ee[g1 * DD + lane];
                sp += p0 + p1;
                sl += l0 + l1;
                se += e0 + e1;
                sm += g_elamm1[g0] + g_elamm1[g1];
                S->pT[w][lane * ST2 + j]     = p0;
                S->pT[w][lane * ST2 + j + 1] = p1;
            }
            if (j < cnt) {
                int g0 = lst[j];
                float p = g_es[g0 * DD + lane];
                sp += p;
                sl += g_elamx[g0 * DD + lane];
                se += g_ee[g0 * DD + lane];
                sm += g_elamm1[g0];
                S->pT[w][lane * ST2 + j] = p;
            }
        } else {
            for (int j = 0; j < cnt; j++) {
                int g0 = lst[j];
                sp += g_es[g0 * DD + lane];
                sl += g_elamx[g0 * DD + lane];
                se += g_ee[g0 * DD + lane];
                sm += g_elamm1[g0];
            }
        }

        float oe = se / fmaxf(cntf, 1e-6f);

        float den = fmaxf(sm, 1e-6f);
        float y   = sl / den;
        float yn  = fmaxf(sqrtf(wsum(y * y)), 1e-6f);
        float arg = clip1(sc * yn);
        float oh  = tanhf(0.5f * atanhf(arg)) * y / (sc * yn);
        float n   = sqrtf(wsum(oh * oh));
        float nm  = fmaxf(n, 1e-6f);
        if (nm > maxn) oh *= maxn / nm;

        float mu = sp / cntf;
        mu /= fmaxf(sqrtf(wsum(mu * mu)), 1e-6f);

        if (cache) {
            S->mu[w][lane] = mu;
            __syncwarp();
            for (int it = 0; it < 5; it++) {
                float asum_d = 0.f, asum_r = 0.f;
                for (int m = lane; m < cnt; m += 32) {
                    float d0 = 0.f, d1 = 0.f;
                    #pragma unroll
                    for (int d = 0; d < DD; d += 2) {
                        d0 = fmaf(S->mu[w][d],     S->pT[w][d * ST2 + m],       d0);
                        d1 = fmaf(S->mu[w][d + 1], S->pT[w][(d + 1) * ST2 + m], d1);
                    }
                    float draw = d0 + d1;
                    float dotc = clip1(draw);
                    float theta = acosf(dotc);
                    float dn2 = 1.0f - dotc * (2.0f * draw - dotc);
                    float dn  = fmaxf(sqrtf(fmaxf(dn2, 0.f)), 1e-6f);
                    float a   = theta / dn;
                    S->a[w][m] = a;
                    asum_d = fmaf(a, dotc, asum_d);
                    asum_r = fmaf(a, draw, asum_r);
                }
                __syncwarp();
                float bt = wsum(asum_d);
                float br = wsum(asum_r);
                float t0 = 0.f, t1 = 0.f;
                int m = 0;
                for (; m + 1 < cnt; m += 2) {
                    t0 = fmaf(S->a[w][m],     S->pT[w][lane * ST2 + m],     t0);
                    t1 = fmaf(S->a[w][m + 1], S->pT[w][lane * ST2 + m + 1], t1);
                }
                if (m < cnt) t0 = fmaf(S->a[w][m], S->pT[w][lane * ST2 + m], t0);
                float mul = S->mu[w][lane];
                float t = fmaf(-bt, mul, t0 + t1);
                float avg = t / cntf;
                float vn2 = wsum(avg * avg);
                float vn  = sqrtf(vn2);
                float vns = fmaxf(vn, 1e-6f);
                float cv = cosf(vn), sv = sinf(vn);
                float mudotavg = (br - bt) / cntf;
                float r   = cv * mul + sv * avg / vns;
                float svv = sv / vns;
                float rn2 = fmaf(cv * cv, 1.0f, fmaf(2.0f * cv * svv, mudotavg, svv * svv * vn2));
                float rn  = fmaxf(sqrtf(rn2), 1e-6f);
                mul = r / rn;
                S->mu[w][lane] = mul;
                __syncwarp();
            }
            mu = S->mu[w][lane];
        } else {
            for (int it = 0; it < 5; it++) {
                float mm = wsum(mu * mu);
                float t = 0.f, bsum = 0.f;
                for (int j = 0; j < cnt; j++) {
                    int g0 = lst[j];
                    float p0 = g_es[g0 * DD + lane];
                    float w0 = wsum(mu * p0);
                    float dc0 = clip1(w0);
                    float th0 = acosf(dc0);
                    float q0 = 1.0f - dc0 * (2.0f * w0 - dc0 * mm);
                    float a0 = th0 / fmaxf(sqrtf(fmaxf(q0, 0.f)), 1e-6f);
                    t    = fmaf(a0, p0, t);
                    bsum = fmaf(-a0, dc0, bsum);
                }
                t = fmaf(bsum, mu, t);
                t /= cntf;
                float vn  = sqrtf(wsum(t * t));
                float vns = fmaxf(vn, 1e-6f);
                mu = cosf(vn) * mu + sinf(vn) * t / vns;
                mu /= fmaxf(sqrtf(wsum(mu * mu)), 1e-6f);
            }
        }
        float os = mu / fmaxf(sqrtf(wsum(mu * mu)), 1e-6f);

        out[i * 96 + lane]      = oh;
        out[i * 96 + 32 + lane] = os;
        out[i * 96 + 64 + lane] = oe;
    }
}

// ---------------- launch ----------------
extern "C" void kernel_launch(void* const* d_in, const int* in_sizes, int n_in,
                              void* d_out, int out_size) {
    const float* x   = (const float*)d_in[0];
    const float* H   = (const float*)d_in[1];
    const float* Wh  = (const float*)d_in[2];
    const float* bh  = (const float*)d_in[3];
    const float* Ws  = (const float*)d_in[4];
    const float* bs  = (const float*)d_in[5];
    const float* We  = (const float*)d_in[6];
    const float* be  = (const float*)d_in[7];
    const float* c_h = (const float*)d_in[8];
    float* out = (float*)d_out;

    k_pre<<<PRE_BLOCKS, 256>>>(x, H, Wh, bh, Ws, bs, We, be, c_h);
    k_agg<<<AGRID, 256>>>(c_h, out);
}